// round 1
// baseline (speedup 1.0000x reference)
#include <cuda_runtime.h>
#include <cuda_bf16.h>

// Hierarchical softmax:
//   phase head:  softmax over 16 logits (W_phase)
//   occ head:    softmax over the 8-row block of W_p2o selected by phase
//   subj head:   softmax over the 16-row block of W_o2s selected by occ class
// Only 40 dot products per row are needed. We bin rows by global occurrence
// class (phase*8 + occ_local, 128 classes) so each block reuses its 40 weight
// rows from SMEM across a 64-row tile (skinny GEMM), then fuses the softmaxes.

#define NBINS   128
#define BIN_CAP 2048
#define HDIM    256
#define NPH     16
#define KOCC    8
#define KSUBJ   16
#define NOUT    40      // 16 + 8 + 16
#define TILE_R  64
#define XS_STRIDE 260   // padded row stride (floats) for X tile in smem
#define WS_STRIDE 264   // padded row stride (floats) for weights in smem
#define CS_STRIDE 41    // logit tile stride (odd -> conflict-free row reads)

__device__ int g_cnt[NBINS];
__device__ int g_bins[NBINS * BIN_CAP];

__global__ void hs_zero() {
    if (threadIdx.x < NBINS) g_cnt[threadIdx.x] = 0;
}

__global__ void hs_scatter(const int* __restrict__ xph,
                           const int* __restrict__ xocc, int n) {
    int i = blockIdx.x * blockDim.x + threadIdx.x;
    if (i < n) {
        int c = xph[i] * KOCC + xocc[i];
        int pos = atomicAdd(&g_cnt[c], 1);
        if (pos < BIN_CAP) g_bins[c * BIN_CAP + pos] = i;
    }
}

__global__ __launch_bounds__(128, 2) void hs_main(
    const float* __restrict__ X,
    const float* __restrict__ Wph,  const float* __restrict__ bph,
    const float* __restrict__ Wp2o, const float* __restrict__ bp2o,
    const float* __restrict__ Wo2s, const float* __restrict__ bo2s,
    const int*   __restrict__ Xsubj,
    float* __restrict__ out, int n)
{
    extern __shared__ float sm[];
    float* ws = sm;                          // [NOUT][WS_STRIDE]
    float* xs = sm + NOUT * WS_STRIDE;       // [TILE_R][XS_STRIDE]
    float* bs = xs + TILE_R * XS_STRIDE;     // [NOUT] biases
    __shared__ int ridx[TILE_R];

    const int c  = blockIdx.x;               // global occurrence class
    int cnt = g_cnt[c]; if (cnt > BIN_CAP) cnt = BIN_CAP;
    const int r0 = blockIdx.y * TILE_R;
    if (r0 >= cnt) return;
    const int nrows = min(TILE_R, cnt - r0);
    const int ph  = c >> 3;                  // phase for every row in this bin
    const int tid = threadIdx.x;

    // biases: [0..16) phase, [16..24) p2o block, [24..40) o2s block
    if (tid < NOUT) {
        float b;
        if (tid < NPH)             b = bph[tid];
        else if (tid < NPH + KOCC) b = bp2o[ph * KOCC + (tid - NPH)];
        else                       b = bo2s[c * KSUBJ + (tid - NPH - KOCC)];
        bs[tid] = b;
    }
    if (tid < TILE_R)
        ridx[tid] = (tid < nrows) ? g_bins[c * BIN_CAP + r0 + tid] : -1;

    // stage the 40 weight rows (float4-coalesced)
    for (int e = tid; e < NOUT * (HDIM / 4); e += 128) {
        int row = e >> 6;          // /64
        int q   = e & 63;
        const float* src;
        if (row < NPH)             src = Wph  + row * HDIM;
        else if (row < NPH + KOCC) src = Wp2o + (ph * KOCC + row - NPH) * HDIM;
        else                       src = Wo2s + (c * KSUBJ + row - NPH - KOCC) * HDIM;
        float4 v = reinterpret_cast<const float4*>(src)[q];
        *reinterpret_cast<float4*>(&ws[row * WS_STRIDE + q * 4]) = v;
    }
    __syncthreads();               // ridx visible

    // stage the X tile (gathered rows, float4-coalesced per row)
    for (int e = tid; e < TILE_R * (HDIM / 4); e += 128) {
        int row = e >> 6;
        int q   = e & 63;
        int gr  = ridx[row];
        float4 v = make_float4(0.f, 0.f, 0.f, 0.f);
        if (gr >= 0) v = reinterpret_cast<const float4*>(X + (size_t)gr * HDIM)[q];
        *reinterpret_cast<float4*>(&xs[row * XS_STRIDE + q * 4]) = v;
    }
    __syncthreads();

    // register-tiled GEMM: 128 thr = 16 row-groups x 8 out-groups,
    // thread tile = 4 rows x 5 outs
    const int tr = tid >> 3;       // 0..15
    const int tc = tid & 7;        // 0..7
    float acc[4][5];
    #pragma unroll
    for (int i = 0; i < 4; i++)
        #pragma unroll
        for (int j = 0; j < 5; j++) acc[i][j] = 0.f;

    const float* xp = xs + (tr * 4) * XS_STRIDE;
    const float* wp = ws + (tc * 5) * WS_STRIDE;

    #pragma unroll 4
    for (int k = 0; k < HDIM; k += 4) {
        float4 xv[4], wv[5];
        #pragma unroll
        for (int i = 0; i < 4; i++)
            xv[i] = *reinterpret_cast<const float4*>(xp + i * XS_STRIDE + k);
        #pragma unroll
        for (int j = 0; j < 5; j++)
            wv[j] = *reinterpret_cast<const float4*>(wp + j * WS_STRIDE + k);
        #pragma unroll
        for (int i = 0; i < 4; i++)
            #pragma unroll
            for (int j = 0; j < 5; j++) {
                acc[i][j] += xv[i].x * wv[j].x;
                acc[i][j] += xv[i].y * wv[j].y;
                acc[i][j] += xv[i].z * wv[j].z;
                acc[i][j] += xv[i].w * wv[j].w;
            }
    }

    // park logits in smem (overlay on xs; all reads of xs are done)
    __syncthreads();
    float* cs = xs;
    #pragma unroll
    for (int i = 0; i < 4; i++)
        #pragma unroll
        for (int j = 0; j < 5; j++)
            cs[(tr * 4 + i) * CS_STRIDE + (tc * 5 + j)] = acc[i][j];
    __syncthreads();

    // fused softmax epilogue: one thread per row
    if (tid < nrows) {
        float l[NOUT];
        #pragma unroll
        for (int o = 0; o < NOUT; o++) l[o] = cs[tid * CS_STRIDE + o] + bs[o];

        // phase softmax over 16
        float m = l[0];
        #pragma unroll
        for (int o = 1; o < NPH; o++) m = fmaxf(m, l[o]);
        float s = 0.f;
        #pragma unroll
        for (int o = 0; o < NPH; o++) s += __expf(l[o] - m);
        float pp = __expf(l[ph] - m) / s;

        // occurrence softmax over 8 (block already selected by bin)
        const int oc = c & 7;
        float m2 = l[NPH];
        #pragma unroll
        for (int o = 1; o < KOCC; o++) m2 = fmaxf(m2, l[NPH + o]);
        float s2 = 0.f;
        #pragma unroll
        for (int o = 0; o < KOCC; o++) s2 += __expf(l[NPH + o] - m2);
        float op = __expf(l[NPH + oc] - m2) / s2;

        // subject softmax over 16
        const int gr = ridx[tid];
        const int sj = Xsubj[gr];
        float m3 = l[NPH + KOCC];
        #pragma unroll
        for (int o = 1; o < KSUBJ; o++) m3 = fmaxf(m3, l[NPH + KOCC + o]);
        float s3 = 0.f;
        #pragma unroll
        for (int o = 0; o < KSUBJ; o++) s3 += __expf(l[NPH + KOCC + o] - m3);
        float sp = __expf(l[NPH + KOCC + sj] - m3) / s3;

        float po = pp * op;
        out[gr]         = pp;
        out[n + gr]     = po;
        out[2 * n + gr] = po * sp;
    }
}

extern "C" void kernel_launch(void* const* d_in, const int* in_sizes, int n_in,
                              void* d_out, int out_size) {
    const float* X    = (const float*)d_in[0];
    const float* Wph  = (const float*)d_in[1];
    const float* bph  = (const float*)d_in[2];
    const float* Wp2o = (const float*)d_in[3];
    const float* bp2o = (const float*)d_in[4];
    const float* Wo2s = (const float*)d_in[5];
    const float* bo2s = (const float*)d_in[6];
    const int* xph  = (const int*)d_in[7];
    const int* xocc = (const int*)d_in[8];
    const int* xsub = (const int*)d_in[9];
    float* out = (float*)d_out;
    const int n = in_sizes[7];           // N rows (count of X_phase)

    const size_t smem = (size_t)(NOUT * WS_STRIDE + TILE_R * XS_STRIDE + 64) * sizeof(float);
    cudaFuncSetAttribute(hs_main, cudaFuncAttributeMaxDynamicSharedMemorySize, (int)smem);

    hs_zero<<<1, 128>>>();
    hs_scatter<<<(n + 255) / 256, 256>>>(xph, xocc, n);
    dim3 grid(NBINS, BIN_CAP / TILE_R);
    hs_main<<<grid, 128, smem>>>(X, Wph, bph, Wp2o, bp2o, Wo2s, bo2s, xsub, out, n);
}

// round 3
// speedup vs baseline: 1.1461x; 1.1461x over previous
#include <cuda_runtime.h>
#include <cuda_bf16.h>

// Hierarchical softmax, bin-by-occurrence-class skinny GEMM.
// Round 2: packed fma.rn.f32x2 mainloop (2 FMA/instr), X transposed in smem
// (row-pairs are contiguous 8B at fixed k), weights pre-duplicated as {w,w}
// pairs in smem so the inner loop has zero packing ops.
// TILE_R=128 rows/block, 256 threads, thread tile 4 rows x 5 outs.

#define NBINS   128
#define BIN_CAP 2048
#define HDIM    256
#define NPH     16
#define KOCC    8
#define KSUBJ   16
#define NOUT    40
#define TILE_R  128
#define THREADS 256
#define XT_STRIDE 132   // floats per k-row of xs_t (128 rows + pad); 528B = 33*16 -> 16B aligned
#define W2_STRIDE 258   // float2 per out-row of ws2
#define CS_STRIDE 41

typedef unsigned long long ull;

__device__ int g_cnt[NBINS];
__device__ int g_bins[NBINS * BIN_CAP];

__device__ __forceinline__ void ffma2(ull& d, ull a, ull b, ull c) {
    asm("fma.rn.f32x2 %0, %1, %2, %3;" : "=l"(d) : "l"(a), "l"(b), "l"(c));
}

__global__ void hs_zero() {
    if (threadIdx.x < NBINS) g_cnt[threadIdx.x] = 0;
}

__global__ void hs_scatter(const int* __restrict__ xph,
                           const int* __restrict__ xocc, int n) {
    int i = blockIdx.x * blockDim.x + threadIdx.x;
    if (i < n) {
        int c = xph[i] * KOCC + xocc[i];
        int pos = atomicAdd(&g_cnt[c], 1);
        if (pos < BIN_CAP) g_bins[c * BIN_CAP + pos] = i;
    }
}

__global__ __launch_bounds__(THREADS, 1) void hs_main(
    const float* __restrict__ X,
    const float* __restrict__ Wph,  const float* __restrict__ bph,
    const float* __restrict__ Wp2o, const float* __restrict__ bp2o,
    const float* __restrict__ Wo2s, const float* __restrict__ bo2s,
    const int*   __restrict__ Xsubj,
    float* __restrict__ out, int n)
{
    extern __shared__ char smraw[];
    float2* ws2 = (float2*)smraw;                          // [NOUT][W2_STRIDE] duplicated pairs
    float*  xst = (float*)(smraw + NOUT * W2_STRIDE * 8);  // [HDIM][XT_STRIDE] transposed X
    float*  bs  = xst + HDIM * XT_STRIDE;                  // [NOUT]
    __shared__ int ridx[TILE_R];

    const int c  = blockIdx.x;
    int cnt = g_cnt[c]; if (cnt > BIN_CAP) cnt = BIN_CAP;
    const int r0 = blockIdx.y * TILE_R;
    if (r0 >= cnt) return;
    const int nrows = min(TILE_R, cnt - r0);
    const int ph  = c >> 3;
    const int tid = threadIdx.x;

    if (tid < NOUT) {
        float b;
        if (tid < NPH)             b = bph[tid];
        else if (tid < NPH + KOCC) b = bp2o[ph * KOCC + (tid - NPH)];
        else                       b = bo2s[c * KSUBJ + (tid - NPH - KOCC)];
        bs[tid] = b;
    }
    if (tid < TILE_R)
        ridx[tid] = (tid < nrows) ? g_bins[c * BIN_CAP + r0 + tid] : -1;

    // stage 40 weight rows as duplicated {w,w} pairs
    for (int e = tid; e < NOUT * (HDIM / 4); e += THREADS) {
        int row = e >> 6;
        int q   = e & 63;
        const float* src;
        if (row < NPH)             src = Wph  + row * HDIM;
        else if (row < NPH + KOCC) src = Wp2o + (ph * KOCC + row - NPH) * HDIM;
        else                       src = Wo2s + (c * KSUBJ + row - NPH - KOCC) * HDIM;
        float4 v = reinterpret_cast<const float4*>(src)[q];
        float2* dst = ws2 + row * W2_STRIDE + 4 * q;
        dst[0] = make_float2(v.x, v.x);
        dst[1] = make_float2(v.y, v.y);
        dst[2] = make_float2(v.z, v.z);
        dst[3] = make_float2(v.w, v.w);
    }
    __syncthreads();   // ridx visible

    // stage X transposed: lane-per-row mapping -> conflict-free STS
    // thread handles row (tid & 127), q = (tid>>7) + 2m
    for (int e = tid; e < TILE_R * (HDIM / 4); e += THREADS) {
        int row = e & (TILE_R - 1);
        int q   = e >> 7;                 // e / TILE_R
        int gr  = ridx[row];
        float4 v = make_float4(0.f, 0.f, 0.f, 0.f);
        if (gr >= 0) v = reinterpret_cast<const float4*>(X + (size_t)gr * HDIM)[q];
        int k = q * 4;
        xst[(k + 0) * XT_STRIDE + row] = v.x;
        xst[(k + 1) * XT_STRIDE + row] = v.y;
        xst[(k + 2) * XT_STRIDE + row] = v.z;
        xst[(k + 3) * XT_STRIDE + row] = v.w;
    }
    __syncthreads();

    // GEMM: 256 thr = 32 row-groups x 8 out-groups; tile = 4 rows x 5 outs
    const int tr = tid >> 3;
    const int tc = tid & 7;
    const float*  xq = xst + tr * 4;
    const float2* wq = ws2 + (tc * 5) * W2_STRIDE;

    ull acc[2][5];
    #pragma unroll
    for (int p = 0; p < 2; p++)
        #pragma unroll
        for (int j = 0; j < 5; j++) acc[p][j] = 0ull;

    #pragma unroll 4
    for (int k = 0; k < HDIM; k++) {
        ulonglong2 xv = *reinterpret_cast<const ulonglong2*>(xq + k * XT_STRIDE);
        #pragma unroll
        for (int j = 0; j < 5; j++) {
            ull w = *reinterpret_cast<const ull*>(wq + j * W2_STRIDE + k);
            ffma2(acc[0][j], xv.x, w, acc[0][j]);
            ffma2(acc[1][j], xv.y, w, acc[1][j]);
        }
    }

    // park logits (overlay on xst; done reading it)
    __syncthreads();
    float* cs = xst;
    #pragma unroll
    for (int p = 0; p < 2; p++)
        #pragma unroll
        for (int j = 0; j < 5; j++) {
            float lo = __uint_as_float((unsigned)(acc[p][j] & 0xffffffffull));
            float hi = __uint_as_float((unsigned)(acc[p][j] >> 32));
            int r = tr * 4 + p * 2;
            int o = tc * 5 + j;
            cs[r * CS_STRIDE + o]       = lo;
            cs[(r + 1) * CS_STRIDE + o] = hi;
        }
    __syncthreads();

    // fused softmax epilogue: one thread per row
    if (tid < nrows) {
        float l[NOUT];
        #pragma unroll
        for (int o = 0; o < NOUT; o++) l[o] = cs[tid * CS_STRIDE + o] + bs[o];

        float m = l[0];
        #pragma unroll
        for (int o = 1; o < NPH; o++) m = fmaxf(m, l[o]);
        float s = 0.f;
        #pragma unroll
        for (int o = 0; o < NPH; o++) s += __expf(l[o] - m);
        float pp = __expf(l[ph] - m) / s;

        const int oc = c & 7;
        float m2 = l[NPH];
        #pragma unroll
        for (int o = 1; o < KOCC; o++) m2 = fmaxf(m2, l[NPH + o]);
        float s2 = 0.f;
        #pragma unroll
        for (int o = 0; o < KOCC; o++) s2 += __expf(l[NPH + o] - m2);
        float op = __expf(l[NPH + oc] - m2) / s2;

        const int gr = ridx[tid];
        const int sj = Xsubj[gr];
        float m3 = l[NPH + KOCC];
        #pragma unroll
        for (int o = 1; o < KSUBJ; o++) m3 = fmaxf(m3, l[NPH + KOCC + o]);
        float s3 = 0.f;
        #pragma unroll
        for (int o = 0; o < KSUBJ; o++) s3 += __expf(l[NPH + KOCC + o] - m3);
        float sp = __expf(l[NPH + KOCC + sj] - m3) / s3;

        float po = pp * op;
        out[gr]         = pp;
        out[n + gr]     = po;
        out[2 * n + gr] = po * sp;
    }
}

extern "C" void kernel_launch(void* const* d_in, const int* in_sizes, int n_in,
                              void* d_out, int out_size) {
    const float* X    = (const float*)d_in[0];
    const float* Wph  = (const float*)d_in[1];
    const float* bph  = (const float*)d_in[2];
    const float* Wp2o = (const float*)d_in[3];
    const float* bp2o = (const float*)d_in[4];
    const float* Wo2s = (const float*)d_in[5];
    const float* bo2s = (const float*)d_in[6];
    const int* xph  = (const int*)d_in[7];
    const int* xocc = (const int*)d_in[8];
    const int* xsub = (const int*)d_in[9];
    float* out = (float*)d_out;
    const int n = in_sizes[7];

    const size_t smem = (size_t)NOUT * W2_STRIDE * 8
                      + (size_t)HDIM * XT_STRIDE * 4
                      + 64 * 4;
    cudaFuncSetAttribute(hs_main, cudaFuncAttributeMaxDynamicSharedMemorySize, (int)smem);

    hs_zero<<<1, 128>>>();
    hs_scatter<<<(n + 255) / 256, 256>>>(xph, xocc, n);
    dim3 grid(NBINS, BIN_CAP / TILE_R);
    hs_main<<<grid, THREADS, smem>>>(X, Wph, bph, Wp2o, bp2o, Wo2s, bo2s, xsub, out, n);
}